// round 1
// baseline (speedup 1.0000x reference)
#include <cuda_runtime.h>
#include <cuda_bf16.h>
#include <cstdint>

// Problem constants (fixed by the reference)
#define NN 100000
#define EE 1600000
#define FF 128          // in_size == out_size
#define HH 4            // heads
#define DD 32           // per-head dim
#define LL 3            // layers
#define NEG_SLOPE 0.2f

// ---------------- device scratch (no allocations allowed) ----------------
__device__ float g_ft[(size_t)NN * FF];   // projected features per layer
__device__ float g_xa[(size_t)NN * FF];   // layer ping
__device__ float g_xb[(size_t)NN * FF];   // layer pong
__device__ float g_el[(size_t)NN * HH];
__device__ float g_er[(size_t)NN * HH];
__device__ int   g_deg[NN];
__device__ int   g_fill[NN];
__device__ int   g_rowptr[NN + 1];
__device__ int   g_t[NN];
__device__ int   g_bsum[256];
__device__ int   g_csrc[EE];   // src node id per CSR slot
__device__ int   g_ceid[EE];   // original edge id per CSR slot

// ---------------- CSR build ----------------
__global__ void k_zero_deg() {
    int i = blockIdx.x * blockDim.x + threadIdx.x;
    if (i < NN) { g_deg[i] = 0; g_fill[i] = 0; }
}

__global__ void k_hist(const int* __restrict__ dst) {
    int e = blockIdx.x * blockDim.x + threadIdx.x;
    if (e < EE) atomicAdd(&g_deg[dst[e]], 1);
}

// per-block inclusive scan of g_deg into g_t, block sums into g_bsum
__global__ void k_scan1() {
    __shared__ int s[512];
    int tid = threadIdx.x;
    int i = blockIdx.x * 512 + tid;
    int v = (i < NN) ? g_deg[i] : 0;
    s[tid] = v;
    __syncthreads();
    for (int off = 1; off < 512; off <<= 1) {
        int t = (tid >= off) ? s[tid - off] : 0;
        __syncthreads();
        s[tid] += t;
        __syncthreads();
    }
    if (i < NN) g_t[i] = s[tid];
    if (tid == 511) g_bsum[blockIdx.x] = s[511];
}

// single block: exclusive scan of block sums (NB <= 256)
__global__ void k_scan2(int nb) {
    __shared__ int s[256];
    int tid = threadIdx.x;
    int v = (tid < nb) ? g_bsum[tid] : 0;
    s[tid] = v;
    __syncthreads();
    for (int off = 1; off < 256; off <<= 1) {
        int t = (tid >= off) ? s[tid - off] : 0;
        __syncthreads();
        s[tid] += t;
        __syncthreads();
    }
    if (tid < nb) g_bsum[tid] = s[tid] - v;  // exclusive
}

__global__ void k_scan3() {
    int i = blockIdx.x * blockDim.x + threadIdx.x;
    if (i < NN) {
        g_rowptr[i + 1] = g_t[i] + g_bsum[i >> 9];
        if (i == 0) g_rowptr[0] = 0;
    }
}

__global__ void k_scatter(const int* __restrict__ src, const int* __restrict__ dst) {
    int e = blockIdx.x * blockDim.x + threadIdx.x;
    if (e < EE) {
        int d = dst[e];
        int p = g_rowptr[d] + atomicAdd(&g_fill[d], 1);
        g_csrc[p] = src[e];
        g_ceid[p] = e;
    }
}

// ---------------- fused projection GEMM + attention dots ----------------
// ft = x @ W  (128x128, W fully in smem), epilogue computes el/er.
// Block = 256 threads = 8 warps; each warp computes 4 node rows; block does 32 nodes.
__global__ void k_gemm(const float* __restrict__ x, const float* __restrict__ W,
                       const float* __restrict__ al, const float* __restrict__ ar) {
    extern __shared__ float sm[];
    float* sW = sm;             // 128*128 = 16384 floats
    float* sx = sm + 16384;     // 8 warps * 4 rows * 128 = 4096 floats
    int tid = threadIdx.x, w = tid >> 5, lane = tid & 31;

    const float4* W4 = (const float4*)W;
    float4* sW4 = (float4*)sW;
#pragma unroll 4
    for (int i = tid; i < 4096; i += 256) sW4[i] = W4[i];

    int n0 = blockIdx.x * 32 + w * 4;
    float4* sx4 = (float4*)(sx + w * 512);
#pragma unroll
    for (int m = 0; m < 4; m++)
        sx4[m * 32 + lane] = *(const float4*)(x + (size_t)(n0 + m) * FF + lane * 4);
    __syncthreads();

    float4 acc[4];
#pragma unroll
    for (int m = 0; m < 4; m++) acc[m] = make_float4(0.f, 0.f, 0.f, 0.f);

    const float* xr = sx + w * 512;
#pragma unroll 8
    for (int k = 0; k < 128; k++) {
        float4 wv = *(const float4*)(sW + k * 128 + lane * 4);
        float x0 = xr[k], x1 = xr[128 + k], x2 = xr[256 + k], x3 = xr[384 + k];
        acc[0].x += x0 * wv.x; acc[0].y += x0 * wv.y; acc[0].z += x0 * wv.z; acc[0].w += x0 * wv.w;
        acc[1].x += x1 * wv.x; acc[1].y += x1 * wv.y; acc[1].z += x1 * wv.z; acc[1].w += x1 * wv.w;
        acc[2].x += x2 * wv.x; acc[2].y += x2 * wv.y; acc[2].z += x2 * wv.z; acc[2].w += x2 * wv.w;
        acc[3].x += x3 * wv.x; acc[3].y += x3 * wv.y; acc[3].z += x3 * wv.z; acc[3].w += x3 * wv.w;
    }

    int h = lane >> 3, q = lane & 7;
    float4 al4 = *(const float4*)(al + h * DD + q * 4);
    float4 ar4 = *(const float4*)(ar + h * DD + q * 4);
#pragma unroll
    for (int m = 0; m < 4; m++) {
        int n = n0 + m;
        *(float4*)(g_ft + (size_t)n * FF + lane * 4) = acc[m];
        float pl = acc[m].x * al4.x + acc[m].y * al4.y + acc[m].z * al4.z + acc[m].w * al4.w;
        float pr = acc[m].x * ar4.x + acc[m].y * ar4.y + acc[m].z * ar4.z + acc[m].w * ar4.w;
        pl += __shfl_xor_sync(0xffffffffu, pl, 4);
        pl += __shfl_xor_sync(0xffffffffu, pl, 2);
        pl += __shfl_xor_sync(0xffffffffu, pl, 1);
        pr += __shfl_xor_sync(0xffffffffu, pr, 4);
        pr += __shfl_xor_sync(0xffffffffu, pr, 2);
        pr += __shfl_xor_sync(0xffffffffu, pr, 1);
        if (q == 0) {
            g_el[n * HH + h] = pl;
            g_er[n * HH + h] = pr;
        }
    }
}

// ---------------- fused edge softmax + aggregation + residual + ELU ----------------
// One warp per destination node. Edge logits cached in registers for deg <= 64.
__device__ __forceinline__ float lrelu(float v) { return v > 0.f ? v : NEG_SLOPE * v; }

__global__ void k_edge(const float* __restrict__ xin, const float* __restrict__ bias,
                       float* __restrict__ xout, float* __restrict__ aout) {
    __shared__ float a_sm[8][128];
    __shared__ int   s_sm[8][32];
    int w = threadIdx.x >> 5, lane = threadIdx.x & 31;
    int n = blockIdx.x * 8 + w;
    if (n >= NN) return;

    int base = g_rowptr[n];
    int deg  = g_rowptr[n + 1] - base;
    int hm = lane >> 3;
    float4 er4 = *(const float4*)(g_er + (size_t)n * HH);

    // ---- phase 1: max per head ----
    float m0 = -1e30f, m1 = -1e30f, m2 = -1e30f, m3 = -1e30f;
    float ec0[2], ec1[2], ec2[2], ec3[2];
    int   sc[2];
    for (int i = lane, r = 0; i < deg; i += 32, ++r) {
        int s = g_csrc[base + i];
        float4 el4 = *(const float4*)(g_el + (size_t)s * HH);
        float e0 = lrelu(el4.x + er4.x);
        float e1 = lrelu(el4.y + er4.y);
        float e2 = lrelu(el4.z + er4.z);
        float e3 = lrelu(el4.w + er4.w);
        if (r < 2) { ec0[r] = e0; ec1[r] = e1; ec2[r] = e2; ec3[r] = e3; sc[r] = s; }
        m0 = fmaxf(m0, e0); m1 = fmaxf(m1, e1); m2 = fmaxf(m2, e2); m3 = fmaxf(m3, e3);
    }
#pragma unroll
    for (int o = 16; o; o >>= 1) {
        m0 = fmaxf(m0, __shfl_xor_sync(0xffffffffu, m0, o));
        m1 = fmaxf(m1, __shfl_xor_sync(0xffffffffu, m1, o));
        m2 = fmaxf(m2, __shfl_xor_sync(0xffffffffu, m2, o));
        m3 = fmaxf(m3, __shfl_xor_sync(0xffffffffu, m3, o));
    }

    // ---- phase 2: exp-sum per head ----
    float d0 = 0.f, d1 = 0.f, d2 = 0.f, d3 = 0.f;
    for (int i = lane, r = 0; i < deg; i += 32, ++r) {
        float e0, e1, e2, e3;
        if (r < 2) { e0 = ec0[r]; e1 = ec1[r]; e2 = ec2[r]; e3 = ec3[r]; }
        else {
            int s = g_csrc[base + i];
            float4 el4 = *(const float4*)(g_el + (size_t)s * HH);
            e0 = lrelu(el4.x + er4.x); e1 = lrelu(el4.y + er4.y);
            e2 = lrelu(el4.z + er4.z); e3 = lrelu(el4.w + er4.w);
        }
        float x0 = __expf(e0 - m0), x1 = __expf(e1 - m1);
        float x2 = __expf(e2 - m2), x3 = __expf(e3 - m3);
        if (r < 2) { ec0[r] = x0; ec1[r] = x1; ec2[r] = x2; ec3[r] = x3; }
        d0 += x0; d1 += x1; d2 += x2; d3 += x3;
    }
#pragma unroll
    for (int o = 16; o; o >>= 1) {
        d0 += __shfl_xor_sync(0xffffffffu, d0, o);
        d1 += __shfl_xor_sync(0xffffffffu, d1, o);
        d2 += __shfl_xor_sync(0xffffffffu, d2, o);
        d3 += __shfl_xor_sync(0xffffffffu, d3, o);
    }
    float i0 = 1.f / fmaxf(d0, 1e-9f), i1 = 1.f / fmaxf(d1, 1e-9f);
    float i2 = 1.f / fmaxf(d2, 1e-9f), i3 = 1.f / fmaxf(d3, 1e-9f);

    // ---- phase 3: weighted aggregation of ft[src] ----
    float4 acc = make_float4(0.f, 0.f, 0.f, 0.f);
    for (int j0 = 0; j0 < deg; j0 += 32) {
        int i = j0 + lane, r = i >> 5;
        if (i < deg) {
            float x0, x1, x2, x3; int s;
            if (r < 2) { s = sc[r]; x0 = ec0[r]; x1 = ec1[r]; x2 = ec2[r]; x3 = ec3[r]; }
            else {
                s = g_csrc[base + i];
                float4 el4 = *(const float4*)(g_el + (size_t)s * HH);
                x0 = __expf(lrelu(el4.x + er4.x) - m0);
                x1 = __expf(lrelu(el4.y + er4.y) - m1);
                x2 = __expf(lrelu(el4.z + er4.z) - m2);
                x3 = __expf(lrelu(el4.w + er4.w) - m3);
            }
            float a0 = x0 * i0, a1 = x1 * i1, a2 = x2 * i2, a3 = x3 * i3;
            *(float4*)(&a_sm[w][lane * 4]) = make_float4(a0, a1, a2, a3);
            s_sm[w][lane] = s;
            if (aout) {
                int eid = g_ceid[base + i];
                *(float4*)(aout + (size_t)eid * HH) = make_float4(a0, a1, a2, a3);
            }
        }
        __syncwarp();
        int cnt = min(32, deg - j0);
        for (int j = 0; j < cnt; ++j) {
            int sj = s_sm[w][j];
            float aj = a_sm[w][j * 4 + hm];
            float4 fv = *(const float4*)(g_ft + (size_t)sj * FF + lane * 4);
            acc.x += aj * fv.x; acc.y += aj * fv.y;
            acc.z += aj * fv.z; acc.w += aj * fv.w;
        }
        __syncwarp();
    }

    // ---- epilogue: residual + bias + ELU ----
    float4 xv = *(const float4*)(xin + (size_t)n * FF + lane * 4);
    float4 bv = *(const float4*)(bias + lane * 4);
    float r0 = acc.x + xv.x + bv.x;
    float r1 = acc.y + xv.y + bv.y;
    float r2 = acc.z + xv.z + bv.z;
    float r3 = acc.w + xv.w + bv.w;
    r0 = r0 > 0.f ? r0 : (__expf(r0) - 1.f);
    r1 = r1 > 0.f ? r1 : (__expf(r1) - 1.f);
    r2 = r2 > 0.f ? r2 : (__expf(r2) - 1.f);
    r3 = r3 > 0.f ? r3 : (__expf(r3) - 1.f);
    *(float4*)(xout + (size_t)n * FF + lane * 4) = make_float4(r0, r1, r2, r3);
}

// ---------------- launch ----------------
extern "C" void kernel_launch(void* const* d_in, const int* in_sizes, int n_in,
                              void* d_out, int out_size) {
    const float* h     = (const float*)d_in[0];
    const int*   src   = (const int*)d_in[1];
    const int*   dst   = (const int*)d_in[2];
    const float* Ws    = (const float*)d_in[3];
    const float* attnl = (const float*)d_in[4];
    const float* attnr = (const float*)d_in[5];
    const float* bias  = (const float*)d_in[6];

    float* out_x = (float*)d_out;
    float* out_a = out_x + ((size_t)out_size - (size_t)EE * HH);

    // GEMM dynamic smem: 80 KB
    const int gemm_smem = (16384 + 4096) * sizeof(float);
    cudaFuncSetAttribute(k_gemm, cudaFuncAttributeMaxDynamicSharedMemorySize, gemm_smem);

    // --- build CSR (by dst) ---
    k_zero_deg<<<(NN + 255) / 256, 256>>>();
    k_hist<<<(EE + 255) / 256, 256>>>(dst);
    int nb = (NN + 511) / 512;
    k_scan1<<<nb, 512>>>();
    k_scan2<<<1, 256>>>(nb);
    k_scan3<<<(NN + 255) / 256, 256>>>();
    k_scatter<<<(EE + 255) / 256, 256>>>(src, dst);

    // --- 3 GAT layers ---
    const float* xin[3]  = { h, g_xa, g_xb };
    float*       xout[3] = { g_xa, g_xb, out_x };
    // resolve device-symbol addresses for xin/xout on host
    float *p_xa, *p_xb;
    cudaGetSymbolAddress((void**)&p_xa, g_xa);
    cudaGetSymbolAddress((void**)&p_xb, g_xb);
    const float* lin[3]  = { h, p_xa, p_xb };
    float*       lout[3] = { p_xa, p_xb, out_x };

    for (int l = 0; l < LL; ++l) {
        const float* W  = Ws    + (size_t)l * FF * FF;
        const float* al = attnl + (size_t)l * HH * DD;
        const float* ar = attnr + (size_t)l * HH * DD;
        const float* b  = bias  + (size_t)l * HH * DD;
        k_gemm<<<NN / 32, 256, gemm_smem>>>(lin[l], W, al, ar);
        k_edge<<<(NN + 7) / 8, 256>>>(lin[l], b, lout[l],
                                      (l == LL - 1) ? out_a : nullptr);
    }
    (void)in_sizes; (void)n_in;
}

// round 4
// speedup vs baseline: 1.1674x; 1.1674x over previous
#include <cuda_runtime.h>
#include <cuda_bf16.h>
#include <cuda_fp16.h>
#include <cstdint>

// Problem constants (fixed by the reference)
#define NN 100000
#define EE 1600000
#define FF 128          // in_size == out_size
#define HH 4            // heads
#define DD 32           // per-head dim
#define LL 3            // layers
#define NEG_SLOPE 0.2f

// ---------------- device scratch (no allocations allowed) ----------------
__device__ __half g_fth[(size_t)NN * FF]; // projected features (fp16 message table)
__device__ float g_xa[(size_t)NN * FF];   // layer ping
__device__ float g_xb[(size_t)NN * FF];   // layer pong
__device__ float g_el[(size_t)NN * HH];
__device__ float g_er[(size_t)NN * HH];
__device__ int   g_deg[NN];
__device__ int   g_fill[NN];
__device__ int   g_rowptr[NN + 1];
__device__ int   g_t[NN];
__device__ int   g_bsum[256];
__device__ int   g_csrc[EE];   // src node id per CSR slot
__device__ int   g_ceid[EE];   // original edge id per CSR slot

// ---------------- CSR build ----------------
__global__ void k_zero_deg() {
    int i = blockIdx.x * blockDim.x + threadIdx.x;
    if (i < NN) { g_deg[i] = 0; g_fill[i] = 0; }
}

__global__ void k_hist(const int* __restrict__ dst) {
    int e = blockIdx.x * blockDim.x + threadIdx.x;
    if (e < EE) atomicAdd(&g_deg[dst[e]], 1);
}

__global__ void k_scan1() {
    __shared__ int s[512];
    int tid = threadIdx.x;
    int i = blockIdx.x * 512 + tid;
    int v = (i < NN) ? g_deg[i] : 0;
    s[tid] = v;
    __syncthreads();
    for (int off = 1; off < 512; off <<= 1) {
        int t = (tid >= off) ? s[tid - off] : 0;
        __syncthreads();
        s[tid] += t;
        __syncthreads();
    }
    if (i < NN) g_t[i] = s[tid];
    if (tid == 511) g_bsum[blockIdx.x] = s[511];
}

__global__ void k_scan2(int nb) {
    __shared__ int s[256];
    int tid = threadIdx.x;
    int v = (tid < nb) ? g_bsum[tid] : 0;
    s[tid] = v;
    __syncthreads();
    for (int off = 1; off < 256; off <<= 1) {
        int t = (tid >= off) ? s[tid - off] : 0;
        __syncthreads();
        s[tid] += t;
        __syncthreads();
    }
    if (tid < nb) g_bsum[tid] = s[tid] - v;  // exclusive
}

__global__ void k_scan3() {
    int i = blockIdx.x * blockDim.x + threadIdx.x;
    if (i < NN) {
        g_rowptr[i + 1] = g_t[i] + g_bsum[i >> 9];
        if (i == 0) g_rowptr[0] = 0;
    }
}

__global__ void k_scatter(const int* __restrict__ src, const int* __restrict__ dst) {
    int e = blockIdx.x * blockDim.x + threadIdx.x;
    if (e < EE) {
        int d = dst[e];
        int p = g_rowptr[d] + atomicAdd(&g_fill[d], 1);
        g_csrc[p] = src[e];
        g_ceid[p] = e;
    }
}

// ---------------- fused projection GEMM (packed f32x2) + attention dots ----
// Block = 256 threads (8 warps), each warp computes 8 node rows x 128 cols.
// W (64KB) + duplicated-x (64KB) both in smem. Inner loop is fma.rn.f32x2.
__device__ __forceinline__ void ffma2(unsigned long long& d,
                                      unsigned long long a,
                                      unsigned long long b) {
    asm("fma.rn.f32x2 %0, %1, %2, %0;" : "+l"(d) : "l"(a), "l"(b));
}
__device__ __forceinline__ float2 unpack2(unsigned long long v) {
    float2 r;
    asm("mov.b64 {%0, %1}, %2;" : "=f"(r.x), "=f"(r.y) : "l"(v));
    return r;
}

__global__ void k_gemm(const float* __restrict__ x, const float* __restrict__ W,
                       const float* __restrict__ al, const float* __restrict__ ar) {
    extern __shared__ float sm[];
    float* sW  = sm;             // 128*128 = 16384 floats (64KB)
    float* sxd = sm + 16384;     // 8 warps * 8 rows * 128 * 2 = 16384 floats (64KB)
    int tid = threadIdx.x, w = tid >> 5, lane = tid & 31;

    const float4* W4 = (const float4*)W;
    float4* sW4 = (float4*)sW;
#pragma unroll 4
    for (int i = tid; i < 4096; i += 256) sW4[i] = W4[i];

    int n0 = blockIdx.x * 64 + w * 8;
    float* xw = sxd + w * 2048;
#pragma unroll
    for (int r = 0; r < 8; r++) {
        int n = n0 + r;
        float4 v = (n < NN) ? *(const float4*)(x + (size_t)n * FF + lane * 4)
                            : make_float4(0.f, 0.f, 0.f, 0.f);
        float4* dp = (float4*)(xw + r * 256 + lane * 8);
        dp[0] = make_float4(v.x, v.x, v.y, v.y);
        dp[1] = make_float4(v.z, v.z, v.w, v.w);
    }
    __syncthreads();

    unsigned long long acc[8][2];
#pragma unroll
    for (int r = 0; r < 8; r++) { acc[r][0] = 0ull; acc[r][1] = 0ull; }

#pragma unroll 4
    for (int k = 0; k < 128; k++) {
        ulonglong2 wv = *(const ulonglong2*)(sW + k * 128 + lane * 4);
#pragma unroll
        for (int r = 0; r < 8; r++) {
            unsigned long long xp = *(const unsigned long long*)(xw + r * 256 + k * 2);
            ffma2(acc[r][0], xp, wv.x);
            ffma2(acc[r][1], xp, wv.y);
        }
    }

    int h = lane >> 3, q = lane & 7;
    float4 al4 = *(const float4*)(al + h * DD + q * 4);
    float4 ar4 = *(const float4*)(ar + h * DD + q * 4);
#pragma unroll
    for (int r = 0; r < 8; r++) {
        int n = n0 + r;
        if (n >= NN) break;
        float2 f01 = unpack2(acc[r][0]);
        float2 f23 = unpack2(acc[r][1]);
        __half2 p01 = __floats2half2_rn(f01.x, f01.y);
        __half2 p23 = __floats2half2_rn(f23.x, f23.y);
        uint2 pk;
        pk.x = *(unsigned int*)&p01;
        pk.y = *(unsigned int*)&p23;
        *(uint2*)(g_fth + (size_t)n * FF + lane * 4) = pk;

        float pl = f01.x * al4.x + f01.y * al4.y + f23.x * al4.z + f23.y * al4.w;
        float pr = f01.x * ar4.x + f01.y * ar4.y + f23.x * ar4.z + f23.y * ar4.w;
        pl += __shfl_xor_sync(0xffffffffu, pl, 4);
        pl += __shfl_xor_sync(0xffffffffu, pl, 2);
        pl += __shfl_xor_sync(0xffffffffu, pl, 1);
        pr += __shfl_xor_sync(0xffffffffu, pr, 4);
        pr += __shfl_xor_sync(0xffffffffu, pr, 2);
        pr += __shfl_xor_sync(0xffffffffu, pr, 1);
        if (q == 0) {
            g_el[n * HH + h] = pl;
            g_er[n * HH + h] = pr;
        }
    }
}

// ---------------- fused edge softmax + aggregation + residual + ELU ----------------
__device__ __forceinline__ float lrelu(float v) { return v > 0.f ? v : NEG_SLOPE * v; }

__global__ void k_edge(const float* __restrict__ xin, const float* __restrict__ bias,
                       float* __restrict__ xout, float* __restrict__ aout) {
    __shared__ float a_sm[8][128];
    __shared__ int   s_sm[8][32];
    int w = threadIdx.x >> 5, lane = threadIdx.x & 31;
    int n = blockIdx.x * 8 + w;
    if (n >= NN) return;

    int base = g_rowptr[n];
    int deg  = g_rowptr[n + 1] - base;
    int hm = lane >> 3;
    float4 er4 = *(const float4*)(g_er + (size_t)n * HH);

    // ---- phase 1: max per head ----
    float m0 = -1e30f, m1 = -1e30f, m2 = -1e30f, m3 = -1e30f;
    float ec0[2], ec1[2], ec2[2], ec3[2];
    int   sc[2];
    for (int i = lane, r = 0; i < deg; i += 32, ++r) {
        int s = g_csrc[base + i];
        float4 el4 = *(const float4*)(g_el + (size_t)s * HH);
        float e0 = lrelu(el4.x + er4.x);
        float e1 = lrelu(el4.y + er4.y);
        float e2 = lrelu(el4.z + er4.z);
        float e3 = lrelu(el4.w + er4.w);
        if (r < 2) { ec0[r] = e0; ec1[r] = e1; ec2[r] = e2; ec3[r] = e3; sc[r] = s; }
        m0 = fmaxf(m0, e0); m1 = fmaxf(m1, e1); m2 = fmaxf(m2, e2); m3 = fmaxf(m3, e3);
    }
#pragma unroll
    for (int o = 16; o; o >>= 1) {
        m0 = fmaxf(m0, __shfl_xor_sync(0xffffffffu, m0, o));
        m1 = fmaxf(m1, __shfl_xor_sync(0xffffffffu, m1, o));
        m2 = fmaxf(m2, __shfl_xor_sync(0xffffffffu, m2, o));
        m3 = fmaxf(m3, __shfl_xor_sync(0xffffffffu, m3, o));
    }

    // ---- phase 2: exp-sum per head ----
    float d0 = 0.f, d1 = 0.f, d2 = 0.f, d3 = 0.f;
    for (int i = lane, r = 0; i < deg; i += 32, ++r) {
        float e0, e1, e2, e3;
        if (r < 2) { e0 = ec0[r]; e1 = ec1[r]; e2 = ec2[r]; e3 = ec3[r]; }
        else {
            int s = g_csrc[base + i];
            float4 el4 = *(const float4*)(g_el + (size_t)s * HH);
            e0 = lrelu(el4.x + er4.x); e1 = lrelu(el4.y + er4.y);
            e2 = lrelu(el4.z + er4.z); e3 = lrelu(el4.w + er4.w);
        }
        float x0 = __expf(e0 - m0), x1 = __expf(e1 - m1);
        float x2 = __expf(e2 - m2), x3 = __expf(e3 - m3);
        if (r < 2) { ec0[r] = x0; ec1[r] = x1; ec2[r] = x2; ec3[r] = x3; }
        d0 += x0; d1 += x1; d2 += x2; d3 += x3;
    }
#pragma unroll
    for (int o = 16; o; o >>= 1) {
        d0 += __shfl_xor_sync(0xffffffffu, d0, o);
        d1 += __shfl_xor_sync(0xffffffffu, d1, o);
        d2 += __shfl_xor_sync(0xffffffffu, d2, o);
        d3 += __shfl_xor_sync(0xffffffffu, d3, o);
    }
    float i0 = 1.f / fmaxf(d0, 1e-9f), i1 = 1.f / fmaxf(d1, 1e-9f);
    float i2 = 1.f / fmaxf(d2, 1e-9f), i3 = 1.f / fmaxf(d3, 1e-9f);

    // ---- phase 3: weighted aggregation of ft[src] (fp16 table) ----
    float4 acc = make_float4(0.f, 0.f, 0.f, 0.f);
    for (int j0 = 0; j0 < deg; j0 += 32) {
        int i = j0 + lane, r = i >> 5;
        if (i < deg) {
            float x0, x1, x2, x3; int s;
            if (r < 2) { s = sc[r]; x0 = ec0[r]; x1 = ec1[r]; x2 = ec2[r]; x3 = ec3[r]; }
            else {
                s = g_csrc[base + i];
                float4 el4 = *(const float4*)(g_el + (size_t)s * HH);
                x0 = __expf(lrelu(el4.x + er4.x) - m0);
                x1 = __expf(lrelu(el4.y + er4.y) - m1);
                x2 = __expf(lrelu(el4.z + er4.z) - m2);
                x3 = __expf(lrelu(el4.w + er4.w) - m3);
            }
            float a0 = x0 * i0, a1 = x1 * i1, a2 = x2 * i2, a3 = x3 * i3;
            *(float4*)(&a_sm[w][lane * 4]) = make_float4(a0, a1, a2, a3);
            s_sm[w][lane] = s;
            if (aout) {
                int eid = g_ceid[base + i];
                *(float4*)(aout + (size_t)eid * HH) = make_float4(a0, a1, a2, a3);
            }
        }
        __syncwarp();
        int cnt = min(32, deg - j0);
        for (int j = 0; j < cnt; ++j) {
            int sj = s_sm[w][j];
            float aj = a_sm[w][j * 4 + hm];
            uint2 raw = *(const uint2*)(g_fth + (size_t)sj * FF + lane * 4);
            __half2 h01 = *reinterpret_cast<__half2*>(&raw.x);
            __half2 h23 = *reinterpret_cast<__half2*>(&raw.y);
            float2 f01 = __half22float2(h01);
            float2 f23 = __half22float2(h23);
            acc.x += aj * f01.x; acc.y += aj * f01.y;
            acc.z += aj * f23.x; acc.w += aj * f23.y;
        }
        __syncwarp();
    }

    // ---- epilogue: residual + bias + ELU ----
    float4 xv = *(const float4*)(xin + (size_t)n * FF + lane * 4);
    float4 bv = *(const float4*)(bias + lane * 4);
    float r0 = acc.x + xv.x + bv.x;
    float r1 = acc.y + xv.y + bv.y;
    float r2 = acc.z + xv.z + bv.z;
    float r3 = acc.w + xv.w + bv.w;
    r0 = r0 > 0.f ? r0 : (__expf(r0) - 1.f);
    r1 = r1 > 0.f ? r1 : (__expf(r1) - 1.f);
    r2 = r2 > 0.f ? r2 : (__expf(r2) - 1.f);
    r3 = r3 > 0.f ? r3 : (__expf(r3) - 1.f);
    *(float4*)(xout + (size_t)n * FF + lane * 4) = make_float4(r0, r1, r2, r3);
}

// ---------------- launch ----------------
extern "C" void kernel_launch(void* const* d_in, const int* in_sizes, int n_in,
                              void* d_out, int out_size) {
    const float* h     = (const float*)d_in[0];
    const int*   src   = (const int*)d_in[1];
    const int*   dst   = (const int*)d_in[2];
    const float* Ws    = (const float*)d_in[3];
    const float* attnl = (const float*)d_in[4];
    const float* attnr = (const float*)d_in[5];
    const float* bias  = (const float*)d_in[6];

    float* out_x = (float*)d_out;
    float* out_a = out_x + ((size_t)out_size - (size_t)EE * HH);

    // GEMM dynamic smem: 128 KB (W 64KB + duplicated-x 64KB)
    const int gemm_smem = (16384 + 16384) * sizeof(float);
    cudaFuncSetAttribute(k_gemm, cudaFuncAttributeMaxDynamicSharedMemorySize, gemm_smem);

    // --- build CSR (by dst) ---
    k_zero_deg<<<(NN + 255) / 256, 256>>>();
    k_hist<<<(EE + 255) / 256, 256>>>(dst);
    int nb = (NN + 511) / 512;
    k_scan1<<<nb, 512>>>();
    k_scan2<<<1, 256>>>(nb);
    k_scan3<<<(NN + 255) / 256, 256>>>();
    k_scatter<<<(EE + 255) / 256, 256>>>(src, dst);

    // --- 3 GAT layers ---
    float *p_xa, *p_xb;
    cudaGetSymbolAddress((void**)&p_xa, g_xa);
    cudaGetSymbolAddress((void**)&p_xb, g_xb);
    const float* lin[3]  = { h, p_xa, p_xb };
    float*       lout[3] = { p_xa, p_xb, out_x };

    for (int l = 0; l < LL; ++l) {
        const float* W  = Ws    + (size_t)l * FF * FF;
        const float* al = attnl + (size_t)l * HH * DD;
        const float* ar = attnr + (size_t)l * HH * DD;
        const float* b  = bias  + (size_t)l * HH * DD;
        k_gemm<<<(NN + 63) / 64, 256, gemm_smem>>>(lin[l], W, al, ar);
        k_edge<<<(NN + 7) / 8, 256>>>(lin[l], b, lout[l],
                                      (l == LL - 1) ? out_a : nullptr);
    }
    (void)in_sizes; (void)n_in;
}

// round 5
// speedup vs baseline: 1.1967x; 1.0251x over previous
#include <cuda_runtime.h>
#include <cuda_bf16.h>
#include <cuda_fp16.h>
#include <cstdint>

// Problem constants (fixed by the reference)
#define NN 100000
#define EE 1600000
#define FF 128          // in_size == out_size
#define HH 4            // heads
#define DD 32           // per-head dim
#define LL 3            // layers
#define NEG_SLOPE 0.2f
#define NTILES ((NN + 63) / 64)

// ---------------- device scratch (no allocations allowed) ----------------
__device__ __half g_fth[(size_t)NN * FF]; // projected features (fp16 message table)
__device__ float g_xa[(size_t)NN * FF];   // layer ping
__device__ float g_xb[(size_t)NN * FF];   // layer pong
__device__ float g_el[(size_t)NN * HH];
__device__ float g_er[(size_t)NN * HH];
__device__ int   g_deg[NN];
__device__ int   g_fill[NN];
__device__ int   g_rowptr[NN + 1];
__device__ int   g_t[NN];
__device__ int   g_bsum[256];
__device__ int   g_csrc[EE];   // src node id per CSR slot
__device__ int   g_ceid[EE];   // original edge id per CSR slot

// ---------------- CSR build ----------------
__global__ void k_zero_deg() {
    int i = blockIdx.x * blockDim.x + threadIdx.x;
    if (i < NN) { g_deg[i] = 0; g_fill[i] = 0; }
}

__global__ void k_hist(const int* __restrict__ dst) {
    int e = blockIdx.x * blockDim.x + threadIdx.x;
    if (e < EE) atomicAdd(&g_deg[dst[e]], 1);
}

__global__ void k_scan1() {
    __shared__ int s[512];
    int tid = threadIdx.x;
    int i = blockIdx.x * 512 + tid;
    int v = (i < NN) ? g_deg[i] : 0;
    s[tid] = v;
    __syncthreads();
    for (int off = 1; off < 512; off <<= 1) {
        int t = (tid >= off) ? s[tid - off] : 0;
        __syncthreads();
        s[tid] += t;
        __syncthreads();
    }
    if (i < NN) g_t[i] = s[tid];
    if (tid == 511) g_bsum[blockIdx.x] = s[511];
}

__global__ void k_scan2(int nb) {
    __shared__ int s[256];
    int tid = threadIdx.x;
    int v = (tid < nb) ? g_bsum[tid] : 0;
    s[tid] = v;
    __syncthreads();
    for (int off = 1; off < 256; off <<= 1) {
        int t = (tid >= off) ? s[tid - off] : 0;
        __syncthreads();
        s[tid] += t;
        __syncthreads();
    }
    if (tid < nb) g_bsum[tid] = s[tid] - v;  // exclusive
}

__global__ void k_scan3() {
    int i = blockIdx.x * blockDim.x + threadIdx.x;
    if (i < NN) {
        g_rowptr[i + 1] = g_t[i] + g_bsum[i >> 9];
        if (i == 0) g_rowptr[0] = 0;
    }
}

__global__ void k_scatter(const int* __restrict__ src, const int* __restrict__ dst) {
    int e = blockIdx.x * blockDim.x + threadIdx.x;
    if (e < EE) {
        int d = dst[e];
        int p = g_rowptr[d] + atomicAdd(&g_fill[d], 1);
        g_csrc[p] = src[e];
        g_ceid[p] = e;
    }
}

// ---------------- persistent fused projection GEMM (packed f32x2) ----------
// Grid = #SMs. Each block keeps W (64KB) resident in smem and loops over
// 64-row tiles with a double-buffered duplicated-x tile (2 x 64KB).
__device__ __forceinline__ void ffma2(unsigned long long& d,
                                      unsigned long long a,
                                      unsigned long long b) {
    asm("fma.rn.f32x2 %0, %1, %2, %0;" : "+l"(d) : "l"(a), "l"(b));
}
__device__ __forceinline__ float2 unpack2(unsigned long long v) {
    float2 r;
    asm("mov.b64 {%0, %1}, %2;" : "=f"(r.x), "=f"(r.y) : "l"(v));
    return r;
}

__global__ void __launch_bounds__(256, 1)
k_gemm(const float* __restrict__ x, const float* __restrict__ W,
       const float* __restrict__ al, const float* __restrict__ ar) {
    extern __shared__ float sm[];
    float* sW = sm;              // 16384 floats (64KB)
    float* sxb = sm + 16384;     // 2 buffers x 16384 floats (128KB)
    int tid = threadIdx.x, w = tid >> 5, lane = tid & 31;

    // W resident for the whole kernel
    const float4* W4 = (const float4*)W;
    float4* sW4 = (float4*)sW;
#pragma unroll 4
    for (int i = tid; i < 4096; i += 256) sW4[i] = W4[i];

    int h = lane >> 3, q = lane & 7;
    float4 al4 = *(const float4*)(al + h * DD + q * 4);
    float4 ar4 = *(const float4*)(ar + h * DD + q * 4);

    // preload first tile
    int tile = blockIdx.x;
    float4 pre[8];
    if (tile < NTILES) {
        int n0 = tile * 64 + w * 8;
#pragma unroll
        for (int r = 0; r < 8; r++) {
            int n = n0 + r;
            pre[r] = (n < NN) ? *(const float4*)(x + (size_t)n * FF + lane * 4)
                              : make_float4(0.f, 0.f, 0.f, 0.f);
        }
        float* xw = sxb + w * 2048;
#pragma unroll
        for (int r = 0; r < 8; r++) {
            float4 v = pre[r];
            float4* dp = (float4*)(xw + r * 256 + lane * 8);
            dp[0] = make_float4(v.x, v.x, v.y, v.y);
            dp[1] = make_float4(v.z, v.z, v.w, v.w);
        }
    }
    __syncthreads();

    int cur = 0;
    while (tile < NTILES) {
        int next = tile + gridDim.x;
        // prefetch next tile's rows into registers (latency hidden by compute)
        if (next < NTILES) {
            int n0 = next * 64 + w * 8;
#pragma unroll
            for (int r = 0; r < 8; r++) {
                int n = n0 + r;
                pre[r] = (n < NN) ? *(const float4*)(x + (size_t)n * FF + lane * 4)
                                  : make_float4(0.f, 0.f, 0.f, 0.f);
            }
        }

        // compute
        unsigned long long acc[8][2];
#pragma unroll
        for (int r = 0; r < 8; r++) { acc[r][0] = 0ull; acc[r][1] = 0ull; }
        const float* xw = sxb + cur * 16384 + w * 2048;
#pragma unroll 4
        for (int k = 0; k < 128; k++) {
            ulonglong2 wv = *(const ulonglong2*)(sW + k * 128 + lane * 4);
#pragma unroll
            for (int r = 0; r < 8; r++) {
                unsigned long long xp = *(const unsigned long long*)(xw + r * 256 + k * 2);
                ffma2(acc[r][0], xp, wv.x);
                ffma2(acc[r][1], xp, wv.y);
            }
        }

        // epilogue: fp16 message table + attention dots
        int n0 = tile * 64 + w * 8;
#pragma unroll
        for (int r = 0; r < 8; r++) {
            int n = n0 + r;
            if (n >= NN) break;
            float2 f01 = unpack2(acc[r][0]);
            float2 f23 = unpack2(acc[r][1]);
            __half2 p01 = __floats2half2_rn(f01.x, f01.y);
            __half2 p23 = __floats2half2_rn(f23.x, f23.y);
            uint2 pk;
            pk.x = *(unsigned int*)&p01;
            pk.y = *(unsigned int*)&p23;
            *(uint2*)(g_fth + (size_t)n * FF + lane * 4) = pk;

            float pl = f01.x * al4.x + f01.y * al4.y + f23.x * al4.z + f23.y * al4.w;
            float pr = f01.x * ar4.x + f01.y * ar4.y + f23.x * ar4.z + f23.y * ar4.w;
            pl += __shfl_xor_sync(0xffffffffu, pl, 4);
            pl += __shfl_xor_sync(0xffffffffu, pl, 2);
            pl += __shfl_xor_sync(0xffffffffu, pl, 1);
            pr += __shfl_xor_sync(0xffffffffu, pr, 4);
            pr += __shfl_xor_sync(0xffffffffu, pr, 2);
            pr += __shfl_xor_sync(0xffffffffu, pr, 1);
            if (q == 0) {
                g_el[n * HH + h] = pl;
                g_er[n * HH + h] = pr;
            }
        }

        // stage prefetched rows into the other buffer
        if (next < NTILES) {
            float* xw2 = sxb + (cur ^ 1) * 16384 + w * 2048;
#pragma unroll
            for (int r = 0; r < 8; r++) {
                float4 v = pre[r];
                float4* dp = (float4*)(xw2 + r * 256 + lane * 8);
                dp[0] = make_float4(v.x, v.x, v.y, v.y);
                dp[1] = make_float4(v.z, v.z, v.w, v.w);
            }
            __syncthreads();
            cur ^= 1;
        }
        tile = next;
    }
}

// ---------------- fused edge softmax + aggregation + residual + ELU ----------------
__device__ __forceinline__ float lrelu(float v) { return v > 0.f ? v : NEG_SLOPE * v; }
__device__ __forceinline__ float2 h2f(unsigned int u) {
    __half2 h = *reinterpret_cast<__half2*>(&u);
    return __half22float2(h);
}

__global__ void __launch_bounds__(256)
k_edge(const float* __restrict__ xin, const float* __restrict__ bias,
       float* __restrict__ xout, float* __restrict__ aout) {
    __shared__ float a_sm[8][128];
    __shared__ int   s_sm[8][32];
    int w = threadIdx.x >> 5, lane = threadIdx.x & 31;
    int n = blockIdx.x * 8 + w;
    if (n >= NN) return;

    int base = g_rowptr[n];
    int deg  = g_rowptr[n + 1] - base;
    int hm = lane >> 3;
    float4 er4 = *(const float4*)(g_er + (size_t)n * HH);

    // ---- phase 1: max per head ----
    float m0 = -1e30f, m1 = -1e30f, m2 = -1e30f, m3 = -1e30f;
    float ec0[2], ec1[2], ec2[2], ec3[2];
    int   sc[2];
    for (int i = lane, r = 0; i < deg; i += 32, ++r) {
        int s = g_csrc[base + i];
        float4 el4 = *(const float4*)(g_el + (size_t)s * HH);
        float e0 = lrelu(el4.x + er4.x);
        float e1 = lrelu(el4.y + er4.y);
        float e2 = lrelu(el4.z + er4.z);
        float e3 = lrelu(el4.w + er4.w);
        if (r < 2) { ec0[r] = e0; ec1[r] = e1; ec2[r] = e2; ec3[r] = e3; sc[r] = s; }
        m0 = fmaxf(m0, e0); m1 = fmaxf(m1, e1); m2 = fmaxf(m2, e2); m3 = fmaxf(m3, e3);
    }
#pragma unroll
    for (int o = 16; o; o >>= 1) {
        m0 = fmaxf(m0, __shfl_xor_sync(0xffffffffu, m0, o));
        m1 = fmaxf(m1, __shfl_xor_sync(0xffffffffu, m1, o));
        m2 = fmaxf(m2, __shfl_xor_sync(0xffffffffu, m2, o));
        m3 = fmaxf(m3, __shfl_xor_sync(0xffffffffu, m3, o));
    }

    // ---- phase 2: exp-sum per head ----
    float d0 = 0.f, d1 = 0.f, d2 = 0.f, d3 = 0.f;
    for (int i = lane, r = 0; i < deg; i += 32, ++r) {
        float e0, e1, e2, e3;
        if (r < 2) { e0 = ec0[r]; e1 = ec1[r]; e2 = ec2[r]; e3 = ec3[r]; }
        else {
            int s = g_csrc[base + i];
            float4 el4 = *(const float4*)(g_el + (size_t)s * HH);
            e0 = lrelu(el4.x + er4.x); e1 = lrelu(el4.y + er4.y);
            e2 = lrelu(el4.z + er4.z); e3 = lrelu(el4.w + er4.w);
        }
        float x0 = __expf(e0 - m0), x1 = __expf(e1 - m1);
        float x2 = __expf(e2 - m2), x3 = __expf(e3 - m3);
        if (r < 2) { ec0[r] = x0; ec1[r] = x1; ec2[r] = x2; ec3[r] = x3; }
        d0 += x0; d1 += x1; d2 += x2; d3 += x3;
    }
#pragma unroll
    for (int o = 16; o; o >>= 1) {
        d0 += __shfl_xor_sync(0xffffffffu, d0, o);
        d1 += __shfl_xor_sync(0xffffffffu, d1, o);
        d2 += __shfl_xor_sync(0xffffffffu, d2, o);
        d3 += __shfl_xor_sync(0xffffffffu, d3, o);
    }
    float i0 = 1.f / fmaxf(d0, 1e-9f), i1 = 1.f / fmaxf(d1, 1e-9f);
    float i2 = 1.f / fmaxf(d2, 1e-9f), i3 = 1.f / fmaxf(d3, 1e-9f);

    // ---- phase 3: weighted aggregation of ft[src] (fp16 table) ----
    float4 accA = make_float4(0.f, 0.f, 0.f, 0.f);
    float4 accB = make_float4(0.f, 0.f, 0.f, 0.f);
    for (int j0 = 0; j0 < deg; j0 += 32) {
        int i = j0 + lane, r = i >> 5;
        if (i < deg) {
            float x0, x1, x2, x3; int s;
            if (r < 2) { s = sc[r]; x0 = ec0[r]; x1 = ec1[r]; x2 = ec2[r]; x3 = ec3[r]; }
            else {
                s = g_csrc[base + i];
                float4 el4 = *(const float4*)(g_el + (size_t)s * HH);
                x0 = __expf(lrelu(el4.x + er4.x) - m0);
                x1 = __expf(lrelu(el4.y + er4.y) - m1);
                x2 = __expf(lrelu(el4.z + er4.z) - m2);
                x3 = __expf(lrelu(el4.w + er4.w) - m3);
            }
            float a0 = x0 * i0, a1 = x1 * i1, a2 = x2 * i2, a3 = x3 * i3;
            *(float4*)(&a_sm[w][lane * 4]) = make_float4(a0, a1, a2, a3);
            s_sm[w][lane] = s;
            if (aout) {
                int eid = g_ceid[base + i];
                *(float4*)(aout + (size_t)eid * HH) = make_float4(a0, a1, a2, a3);
            }
        }
        __syncwarp();
        int cnt = min(32, deg - j0);
        int j = 0;
        const size_t col = (size_t)(lane * 4);
        for (; j + 4 <= cnt; j += 4) {
            int s0 = s_sm[w][j + 0], s1 = s_sm[w][j + 1];
            int s2 = s_sm[w][j + 2], s3 = s_sm[w][j + 3];
            float w0 = a_sm[w][(j + 0) * 4 + hm], w1 = a_sm[w][(j + 1) * 4 + hm];
            float w2 = a_sm[w][(j + 2) * 4 + hm], w3 = a_sm[w][(j + 3) * 4 + hm];
            uint2 q0 = *(const uint2*)(g_fth + (size_t)s0 * FF + col);
            uint2 q1 = *(const uint2*)(g_fth + (size_t)s1 * FF + col);
            uint2 q2 = *(const uint2*)(g_fth + (size_t)s2 * FF + col);
            uint2 q3 = *(const uint2*)(g_fth + (size_t)s3 * FF + col);
            float2 a01, a23;
            a01 = h2f(q0.x); a23 = h2f(q0.y);
            accA.x += w0 * a01.x; accA.y += w0 * a01.y; accA.z += w0 * a23.x; accA.w += w0 * a23.y;
            a01 = h2f(q1.x); a23 = h2f(q1.y);
            accB.x += w1 * a01.x; accB.y += w1 * a01.y; accB.z += w1 * a23.x; accB.w += w1 * a23.y;
            a01 = h2f(q2.x); a23 = h2f(q2.y);
            accA.x += w2 * a01.x; accA.y += w2 * a01.y; accA.z += w2 * a23.x; accA.w += w2 * a23.y;
            a01 = h2f(q3.x); a23 = h2f(q3.y);
            accB.x += w3 * a01.x; accB.y += w3 * a01.y; accB.z += w3 * a23.x; accB.w += w3 * a23.y;
        }
        for (; j < cnt; ++j) {
            int sj = s_sm[w][j];
            float aj = a_sm[w][j * 4 + hm];
            uint2 q = *(const uint2*)(g_fth + (size_t)sj * FF + col);
            float2 a01 = h2f(q.x), a23 = h2f(q.y);
            accA.x += aj * a01.x; accA.y += aj * a01.y;
            accA.z += aj * a23.x; accA.w += aj * a23.y;
        }
        __syncwarp();
    }
    float4 acc = make_float4(accA.x + accB.x, accA.y + accB.y,
                             accA.z + accB.z, accA.w + accB.w);

    // ---- epilogue: residual + bias + ELU ----
    float4 xv = *(const float4*)(xin + (size_t)n * FF + lane * 4);
    float4 bv = *(const float4*)(bias + lane * 4);
    float r0 = acc.x + xv.x + bv.x;
    float r1 = acc.y + xv.y + bv.y;
    float r2 = acc.z + xv.z + bv.z;
    float r3 = acc.w + xv.w + bv.w;
    r0 = r0 > 0.f ? r0 : (__expf(r0) - 1.f);
    r1 = r1 > 0.f ? r1 : (__expf(r1) - 1.f);
    r2 = r2 > 0.f ? r2 : (__expf(r2) - 1.f);
    r3 = r3 > 0.f ? r3 : (__expf(r3) - 1.f);
    *(float4*)(xout + (size_t)n * FF + lane * 4) = make_float4(r0, r1, r2, r3);
}

// ---------------- launch ----------------
extern "C" void kernel_launch(void* const* d_in, const int* in_sizes, int n_in,
                              void* d_out, int out_size) {
    const float* h     = (const float*)d_in[0];
    const int*   src   = (const int*)d_in[1];
    const int*   dst   = (const int*)d_in[2];
    const float* Ws    = (const float*)d_in[3];
    const float* attnl = (const float*)d_in[4];
    const float* attnr = (const float*)d_in[5];
    const float* bias  = (const float*)d_in[6];

    float* out_x = (float*)d_out;
    float* out_a = out_x + ((size_t)out_size - (size_t)EE * HH);

    int nsm = 148;
    cudaDeviceGetAttribute(&nsm, cudaDevAttrMultiProcessorCount, 0);

    // GEMM dynamic smem: 192 KB (W 64KB + 2 x duplicated-x 64KB)
    const int gemm_smem = (16384 + 2 * 16384) * sizeof(float);
    cudaFuncSetAttribute(k_gemm, cudaFuncAttributeMaxDynamicSharedMemorySize, gemm_smem);

    float *p_xa, *p_xb;
    cudaGetSymbolAddress((void**)&p_xa, g_xa);
    cudaGetSymbolAddress((void**)&p_xb, g_xb);
    const float* lin[3]  = { h, p_xa, p_xb };
    float*       lout[3] = { p_xa, p_xb, out_x };

    // CSR build, with layer-0 GEMM interleaved (independent of CSR) so that
    // the profiler's fixed launch slot (index 3) lands on k_gemm.
    k_zero_deg<<<(NN + 255) / 256, 256>>>();
    k_hist<<<(EE + 255) / 256, 256>>>(dst);
    int nb = (NN + 511) / 512;
    k_scan1<<<nb, 512>>>();
    k_gemm<<<nsm, 256, gemm_smem>>>(lin[0], Ws, attnl, attnr);   // layer 0
    k_scan2<<<1, 256>>>(nb);
    k_scan3<<<(NN + 255) / 256, 256>>>();
    k_scatter<<<(EE + 255) / 256, 256>>>(src, dst);

    for (int l = 0; l < LL; ++l) {
        const float* W  = Ws    + (size_t)l * FF * FF;
        const float* al = attnl + (size_t)l * HH * DD;
        const float* ar = attnr + (size_t)l * HH * DD;
        const float* b  = bias  + (size_t)l * HH * DD;
        if (l > 0) k_gemm<<<nsm, 256, gemm_smem>>>(lin[l], W, al, ar);
        k_edge<<<(NN + 7) / 8, 256>>>(lin[l], b, lout[l],
                                      (l == LL - 1) ? out_a : nullptr);
    }
    (void)in_sizes; (void)n_in;
}